// round 13
// baseline (speedup 1.0000x reference)
#include <cuda_runtime.h>
#include <cuda_bf16.h>
#include <cstdint>
#include <cfloat>

#define BATCH 16
#define CH    512
#define NN    1681
#define CK    256
#define MQK   512
#define NPADC 1792            /* padded n columns */
#define NPP   896             /* pair rows for 1792 */
#define EPSV  1e-5f
#define SCALE 0.0625f         /* 256^-0.5 */

// ---------------- scratch (uint32 = packed bf16x2 unless noted) ----------------
__device__ uint32_t g_Wp[(CH / 2) * MQK];                       // [kp][m] pairs along C
__device__ float    g_bias[MQK];
__device__ uint32_t g_xk[(size_t)BATCH * (CH / 2) * NPADC];     // [b][kp][n] pairs along C
__device__ uint32_t g_xvT[(size_t)BATCH * NPP * CH];            // [b][mp][c] pairs along N
__device__ uint32_t g_QKp[(size_t)BATCH * 256 * NPADC];         // [b][pg][n]; Q pg<128, K pg>=128
__device__ uint32_t g_P[(size_t)BATCH * NN * NPP];              // [b][n][mp] bf16-pair P
__device__ uint32_t g_simfT[(size_t)BATCH * NPP * NPADC];       // [b][mp][n] bf16-pair sim_final^T
__device__ float    g_minv[BATCH * NN];
__device__ float    g_s1[BATCH * NN];
__device__ float    g_s2[BATCH * NN];

// ---------------- helpers ----------------
__device__ __forceinline__ uint32_t packbf(float lo, float hi) {
    __nv_bfloat162 t = __floats2bfloat162_rn(lo, hi);
    return *reinterpret_cast<uint32_t*>(&t);
}
__device__ __forceinline__ float2 unpackbf(uint32_t u) {
    __nv_bfloat162 t = *reinterpret_cast<__nv_bfloat162*>(&u);
    return make_float2(__bfloat162float(t.x), __bfloat162float(t.y));
}
__device__ __forceinline__ void mma_bf16(float c[4], const uint32_t a[4], const uint32_t b[2]) {
    asm volatile(
        "mma.sync.aligned.m16n8k16.row.col.f32.bf16.bf16.f32 "
        "{%0,%1,%2,%3}, {%4,%5,%6,%7}, {%8,%9}, {%0,%1,%2,%3};\n"
        : "+f"(c[0]), "+f"(c[1]), "+f"(c[2]), "+f"(c[3])
        : "r"(a[0]), "r"(a[1]), "r"(a[2]), "r"(a[3]), "r"(b[0]), "r"(b[1]));
}
__device__ __forceinline__ void atomicMinFloat(float* addr, float value) {
    if (value >= 0.f) atomicMin((int*)addr, __float_as_int(value));
    else              atomicMax((unsigned int*)addr, __float_as_uint(value));
}
__device__ __forceinline__ void cpa16(void* s, const uint32_t* g) {
    uint32_t sa = (uint32_t)__cvta_generic_to_shared(s);
    asm volatile("cp.async.cg.shared.global [%0], [%1], 16;" :: "r"(sa), "l"(g));
}
#define CP_COMMIT() asm volatile("cp.async.commit_group;")
#define CP_WAIT0()  asm volatile("cp.async.wait_group 0;")

typedef uint32_t Tile[32][136];
#define TILE_WORDS (32 * 136)
#define SMEM_GEMM  (4 * TILE_WORDS * 4)   /* 69632 bytes */

// issue one 32-row x 128-col uint32 tile per operand (4x cp.async 16B per thread each)
#define ISSUE_TILE(DA, DB, SA, STA, SB, STB)                                   \
    _Pragma("unroll")                                                          \
    for (int it = 0; it < 4; it++) {                                           \
        int li = threadIdx.x + it * 256;                                       \
        int row = li >> 5, c4 = (li & 31) * 4;                                 \
        cpa16(&DA[row][c4], (SA) + (size_t)row * (STA) + c4);                  \
        cpa16(&DB[row][c4], (SB) + (size_t)row * (STB) + c4);                  \
    }

// single-sync 2-stage pipeline over NSTEP 64-k chunks (32 pair rows each)
#define PIPE_LOOP(NSTEP, STA, STB)                                             \
    ISSUE_TILE(As[0], Bs[0], srcA0, (STA), srcB0, (STB));                      \
    CP_COMMIT();                                                               \
    for (int s = 0; s < (NSTEP); s++) {                                        \
        int buf = s & 1;                                                       \
        CP_WAIT0();                                                            \
        __syncthreads();                                                       \
        if (s + 1 < (NSTEP)) {                                                 \
            const uint32_t* sa_ = srcA0 + (size_t)(s + 1) * 32 * (STA);        \
            const uint32_t* sb_ = srcB0 + (size_t)(s + 1) * 32 * (STB);        \
            ISSUE_TILE(As[buf ^ 1], Bs[buf ^ 1], sa_, (STA), sb_, (STB));      \
            CP_COMMIT();                                                       \
        }                                                                      \
        FRAG_MMA_LOOP(As[buf], Bs[buf])                                        \
    }

// fragment compute: tile 128x128, k=64 (32 pair rows), 8 warps (4x2), 2x8 m16n8k16 x4
#define FRAG_MMA_LOOP(AS, BS)                                                  \
    _Pragma("unroll")                                                          \
    for (int kk = 0; kk < 4; kk++) {                                           \
        const int kpb = kk * 8;                                                \
        uint32_t af[2][4], bfr[8][2];                                          \
        _Pragma("unroll")                                                      \
        for (int i = 0; i < 2; i++) {                                          \
            int mm = warp_m * 32 + i * 16 + r;                                 \
            af[i][0] = AS[kpb + cc][mm];                                       \
            af[i][1] = AS[kpb + cc][mm + 8];                                   \
            af[i][2] = AS[kpb + cc + 4][mm];                                   \
            af[i][3] = AS[kpb + cc + 4][mm + 8];                               \
        }                                                                      \
        _Pragma("unroll")                                                      \
        for (int j = 0; j < 8; j++) {                                          \
            int nn2 = warp_n * 64 + j * 8 + r;                                 \
            bfr[j][0] = BS[kpb + cc][nn2];                                     \
            bfr[j][1] = BS[kpb + cc + 4][nn2];                                 \
        }                                                                      \
        _Pragma("unroll")                                                      \
        for (int i = 0; i < 2; i++)                                            \
            _Pragma("unroll")                                                  \
            for (int j = 0; j < 8; j++) mma_bf16(acc[i][j], af[i], bfr[j]);    \
    }

#define ACC_INIT()                                                             \
    float acc[2][8][4];                                                        \
    _Pragma("unroll")                                                          \
    for (int i = 0; i < 2; i++)                                                \
        _Pragma("unroll")                                                      \
        for (int j = 0; j < 8; j++)                                            \
            _Pragma("unroll")                                                  \
            for (int q = 0; q < 4; q++) acc[i][j][q] = 0.f;

#define WARP_VARS()                                                            \
    const int tid = threadIdx.x;                                               \
    const int lane = tid & 31, wid = tid >> 5;                                 \
    const int warp_m = wid >> 1, warp_n = wid & 1;                             \
    const int r = lane >> 2, cc = lane & 3;

#define SMEM_TILES()                                                           \
    extern __shared__ uint32_t dyn_smem[];                                     \
    Tile* As = reinterpret_cast<Tile*>(dyn_smem);                              \
    Tile* Bs = reinterpret_cast<Tile*>(dyn_smem + 2 * TILE_WORDS);

// ---------------- pack: weights + bias + stats reset ----------------
__global__ void pack_misc_kernel(const float* __restrict__ Wq, const float* __restrict__ bq,
                                 const float* __restrict__ Wk, const float* __restrict__ bk) {
    int idx = blockIdx.x * blockDim.x + threadIdx.x;
    if (idx < (CH / 2) * MQK) {
        int m = idx & (MQK - 1), kp = idx >> 9;
        float a = (m < CK) ? Wq[m * CH + 2 * kp]     : Wk[(m - CK) * CH + 2 * kp];
        float b = (m < CK) ? Wq[m * CH + 2 * kp + 1] : Wk[(m - CK) * CH + 2 * kp + 1];
        g_Wp[kp * MQK + m] = packbf(a, b);
    }
    if (idx < MQK) g_bias[idx] = (idx < CK) ? bq[idx] : bk[idx - CK];
    if (idx < BATCH * NN) {
        g_minv[idx] = FLT_MAX;
        g_s1[idx] = 0.f;
        g_s2[idx] = 0.f;
    }
}

// ---------------- pack: x -> pairs along C, [b][kp][n] ----------------
__global__ void pack_xk_kernel(const float* __restrict__ x) {
    int n = blockIdx.x * 256 + threadIdx.x;
    int kp = blockIdx.y, b = blockIdx.z;
    uint32_t v = 0;
    if (n < NN) {
        const float* xb = x + (size_t)b * CH * NN;
        v = packbf(xb[(size_t)(2 * kp) * NN + n], xb[(size_t)(2 * kp + 1) * NN + n]);
    }
    g_xk[((size_t)b * (CH / 2) + kp) * NPADC + n] = v;
}

// ---------------- pack: x -> transposed pairs along N, [b][mp][c] ----------------
__global__ void pack_xvT_kernel(const float* __restrict__ x) {
    __shared__ uint32_t T[32][33];
    int mp0 = blockIdx.x * 32;                // 27 tiles -> 864 rows
    int c0  = blockIdx.y * 32;
    int b   = blockIdx.z;
    int tx = threadIdx.x, ty = threadIdx.y;   // (32, 8)
    const float* xb = x + (size_t)b * CH * NN;
#pragma unroll
    for (int p = 0; p < 4; p++) {
        int c = c0 + p * 8 + ty;
        int m = 2 * (mp0 + tx);
        float f0 = 0.f, f1 = 0.f;
        if (m < NN)     f0 = xb[(size_t)c * NN + m];
        if (m + 1 < NN) f1 = xb[(size_t)c * NN + m + 1];
        T[tx][p * 8 + ty] = packbf(f0, f1);
    }
    __syncthreads();
#pragma unroll
    for (int p = 0; p < 4; p++) {
        int row = p * 8 + ty;
        g_xvT[((size_t)b * NPP + mp0 + row) * CH + c0 + tx] = T[row][tx];
    }
}

// =====================================================================
// GEMM1: QK = Wqk @ xf + bias -> bf16 (m, m+8)-pairs  [b][pg][n]
// =====================================================================
__global__ __launch_bounds__(256, 2) void gemm1_kernel() {
    SMEM_TILES();
    const int b  = blockIdx.z;
    const int m0 = blockIdx.y * 128;
    const int n0 = blockIdx.x * 128;
    WARP_VARS();
    ACC_INIT();

    const uint32_t* srcA0 = g_Wp + (size_t)0 * MQK + m0;
    const uint32_t* srcB0 = g_xk + (size_t)b * (CH / 2) * NPADC + n0;

    PIPE_LOOP(CH / 64, MQK, NPADC)

    uint32_t* outp = g_QKp + (size_t)b * 256 * NPADC;
#pragma unroll
    for (int i = 0; i < 2; i++) {
        int m_lo = m0 + warp_m * 32 + i * 16 + r;
        int pg = (m_lo >> 4) * 8 + r;
        float b_lo = g_bias[m_lo], b_hi = g_bias[m_lo + 8];
#pragma unroll
        for (int j = 0; j < 8; j++) {
            int n = n0 + warp_n * 64 + j * 8 + 2 * cc;
            uint2 u;
            u.x = packbf(acc[i][j][0] + b_lo, acc[i][j][2] + b_hi);
            u.y = packbf(acc[i][j][1] + b_lo, acc[i][j][3] + b_hi);
            *reinterpret_cast<uint2*>(&outp[(size_t)pg * NPADC + n]) = u;
        }
    }
}

// =====================================================================
// GEMM2: P = (Q^T K)*scale*fg -> bf16 pairs [b][n][mp] + fused row stats
// =====================================================================
__global__ __launch_bounds__(256, 2) void gemm2_kernel(const float* __restrict__ fg) {
    SMEM_TILES();
    const int b  = blockIdx.z;
    const int n0 = blockIdx.y * 128;
    const int m0 = blockIdx.x * 128;
    WARP_VARS();
    ACC_INIT();

    const uint32_t* srcA0 = g_QKp + (size_t)b * 256 * NPADC + n0;
    const uint32_t* srcB0 = g_QKp + ((size_t)b * 256 + 128) * NPADC + m0;

    PIPE_LOOP(CK / 64, NPADC, NPADC)

    const float* FG = fg + (size_t)b * NN * NN;
    uint32_t* Pp = g_P + (size_t)b * NN * NPP;
#pragma unroll
    for (int i = 0; i < 2; i++)
#pragma unroll
        for (int h = 0; h < 2; h++) {
            int gn = n0 + warp_m * 32 + i * 16 + r + h * 8;
            bool rowvalid = gn < NN;
            size_t rowoff = (size_t)gn * NN;
            float mn = FLT_MAX, s1 = 0.f, s2 = 0.f;
#pragma unroll
            for (int j = 0; j < 8; j++) {
                int gm = m0 + warp_n * 64 + j * 8 + 2 * cc;
                if (rowvalid && gm < NN) {
                    float f0 = FG[rowoff + gm];
                    float p0 = acc[i][j][2 * h] * SCALE * f0;
                    mn = fminf(mn, p0); s1 += p0 * f0; s2 += f0;
                    float p1 = 0.f;
                    if (gm + 1 < NN) {
                        float f1 = FG[rowoff + gm + 1];
                        p1 = acc[i][j][2 * h + 1] * SCALE * f1;
                        mn = fminf(mn, p1); s1 += p1 * f1; s2 += f1;
                    }
                    Pp[(size_t)gn * NPP + (gm >> 1)] = packbf(p0, p1);
                }
            }
            mn = fminf(mn, __shfl_xor_sync(0xffffffffu, mn, 1));
            mn = fminf(mn, __shfl_xor_sync(0xffffffffu, mn, 2));
            s1 += __shfl_xor_sync(0xffffffffu, s1, 1);
            s1 += __shfl_xor_sync(0xffffffffu, s1, 2);
            s2 += __shfl_xor_sync(0xffffffffu, s2, 1);
            s2 += __shfl_xor_sync(0xffffffffu, s2, 2);
            if (cc == 0 && rowvalid) {
                atomicMinFloat(&g_minv[b * NN + gn], mn);
                atomicAdd(&g_s1[b * NN + gn], s1);
                atomicAdd(&g_s2[b * NN + gn], s2);
            }
        }
}

// =====================================================================
// simf: sim_final = (P - min)*fg*inv + bg -> bf16 pairs TRANSPOSED [b][mp][n]
// =====================================================================
__global__ void simf_kernel(const float* __restrict__ fg, const float* __restrict__ bg) {
    __shared__ uint32_t T[32][33];
    __shared__ float sMin[32], sInv[32];
    const int mp0 = blockIdx.x * 32;          // 27 tiles -> 864 rows
    const int n0  = blockIdx.y * 32;          // 53 tiles -> 1696
    const int b   = blockIdx.z;
    const int tx = threadIdx.x, ty = threadIdx.y;
    const int tid = ty * 32 + tx;

    if (tid < 32) {
        int n = n0 + tid;
        if (n < NN) {
            float mn = g_minv[b * NN + n];
            sMin[tid] = mn;
            sInv[tid] = 1.f / (g_s1[b * NN + n] - mn * g_s2[b * NN + n] + EPSV);
        } else {
            sMin[tid] = 0.f; sInv[tid] = 0.f;
        }
    }
    __syncthreads();

    const float* FG = fg + (size_t)b * NN * NN;
    const float* BG = bg + (size_t)b * NN * NN;
    const uint32_t* Pp = g_P + (size_t)b * NN * NPP;
#pragma unroll
    for (int p = 0; p < 4; p++) {
        int ny = p * 8 + ty;
        int n = n0 + ny;
        int mp = mp0 + tx, m = 2 * mp;
        float v0 = 0.f, v1 = 0.f;
        if (n < NN && m < NN) {
            float2 pv = unpackbf(Pp[(size_t)n * NPP + mp]);
            size_t a = (size_t)n * NN + m;
            float mn = sMin[ny], inv = sInv[ny];
            v0 = (pv.x - mn) * FG[a] * inv + BG[a];
            if (m + 1 < NN)
                v1 = (pv.y - mn) * FG[a + 1] * inv + BG[a + 1];
        }
        T[tx][ny] = packbf(v0, v1);
    }
    __syncthreads();
#pragma unroll
    for (int p = 0; p < 4; p++) {
        int row = p * 8 + ty;
        g_simfT[((size_t)b * NPP + mp0 + row) * NPADC + n0 + tx] = T[row][tx];
    }
}

// =====================================================================
// GEMM3 (transposed): out[c][n] = gamma * sum_m V_pair @ simf_T + x[c][n]
// =====================================================================
__global__ __launch_bounds__(256, 2) void gemm3_kernel(const float* __restrict__ x,
                                                       const float* __restrict__ gamma,
                                                       float* __restrict__ out) {
    SMEM_TILES();
    const int b  = blockIdx.z;
    const int c0 = blockIdx.x * 128;
    const int n0 = blockIdx.y * 128;
    WARP_VARS();
    ACC_INIT();

    const uint32_t* srcA0 = g_xvT   + (size_t)b * NPP * CH + c0;
    const uint32_t* srcB0 = g_simfT + (size_t)b * NPP * NPADC + n0;

    PIPE_LOOP(27, CH, NPADC)   // 27*32 = 864 pair rows >= ceil(1681/2)

    const float g = gamma[0];
    const float* xf = x + (size_t)b * CH * NN;
    float* outb = out + (size_t)b * CH * NN;
#pragma unroll
    for (int i = 0; i < 2; i++)
#pragma unroll
        for (int h = 0; h < 2; h++) {
            int gc = c0 + warp_m * 32 + i * 16 + r + h * 8;
            size_t rowoff = (size_t)gc * NN;
#pragma unroll
            for (int j = 0; j < 8; j++) {
                int gn = n0 + warp_n * 64 + j * 8 + 2 * cc;
                if (gn < NN)
                    outb[rowoff + gn]     = g * acc[i][j][2 * h]     + xf[rowoff + gn];
                if (gn + 1 < NN)
                    outb[rowoff + gn + 1] = g * acc[i][j][2 * h + 1] + xf[rowoff + gn + 1];
            }
        }
}

// ---------------- launch ----------------
extern "C" void kernel_launch(void* const* d_in, const int* in_sizes, int n_in,
                              void* d_out, int out_size) {
    const float* x     = (const float*)d_in[0];
    const float* fg    = (const float*)d_in[1];
    const float* bg    = (const float*)d_in[2];
    const float* Wq    = (const float*)d_in[3];
    const float* bq    = (const float*)d_in[4];
    const float* Wk    = (const float*)d_in[5];
    const float* bk    = (const float*)d_in[6];
    const float* gamma = (const float*)d_in[7];
    float* out = (float*)d_out;

    static bool attr_done = false;
    if (!attr_done) {
        cudaFuncSetAttribute(gemm1_kernel, cudaFuncAttributeMaxDynamicSharedMemorySize, SMEM_GEMM);
        cudaFuncSetAttribute(gemm2_kernel, cudaFuncAttributeMaxDynamicSharedMemorySize, SMEM_GEMM);
        cudaFuncSetAttribute(gemm3_kernel, cudaFuncAttributeMaxDynamicSharedMemorySize, SMEM_GEMM);
        attr_done = true;
    }

    pack_misc_kernel<<<((CH / 2) * MQK + 255) / 256, 256>>>(Wq, bq, Wk, bk);
    pack_xk_kernel<<<dim3(7, CH / 2, BATCH), 256>>>(x);
    pack_xvT_kernel<<<dim3(27, 16, BATCH), dim3(32, 8)>>>(x);

    gemm1_kernel<<<dim3(14, 4, BATCH), 256, SMEM_GEMM>>>();
    gemm2_kernel<<<dim3(14, 14, BATCH), 256, SMEM_GEMM>>>(fg);
    simf_kernel<<<dim3(27, 53, BATCH), dim3(32, 8)>>>(fg, bg);
    gemm3_kernel<<<dim3(4, 14, BATCH), 256, SMEM_GEMM>>>(x, gamma, out);
}

// round 14
// speedup vs baseline: 1.3707x; 1.3707x over previous
#include <cuda_runtime.h>
#include <cuda_bf16.h>
#include <cstdint>
#include <cfloat>

#define BATCH 16
#define CH    512
#define NN    1681
#define CK    256
#define MQK   512
#define NPADC 1792            /* padded n columns */
#define NPP   896             /* pair rows for 1792 */
#define EPSV  1e-5f
#define SCALE 0.0625f         /* 256^-0.5 */

// ---------------- scratch (uint32 = packed bf16x2 unless noted) ----------------
__device__ uint32_t g_Wp[(CH / 2) * MQK];                       // [kp][m] pairs along C
__device__ float    g_bias[MQK];
__device__ uint32_t g_xk[(size_t)BATCH * (CH / 2) * NPADC];     // [b][kp][n] pairs along C
__device__ uint32_t g_xvT[(size_t)BATCH * NPP * CH];            // [b][mp][c] pairs along N
__device__ uint32_t g_QKp[(size_t)BATCH * 256 * NPADC];         // [b][pg][n]; Q pg<128, K pg>=128
__device__ uint32_t g_P[(size_t)BATCH * NN * NPP];              // [b][n][mp] bf16-pair P
__device__ uint32_t g_simfT[(size_t)BATCH * NPP * NPADC];       // [b][mp][n] bf16-pair sim_final^T
__device__ float    g_minv[BATCH * NN];
__device__ float    g_s1[BATCH * NN];
__device__ float    g_s2[BATCH * NN];

// ---------------- helpers ----------------
__device__ __forceinline__ uint32_t packbf(float lo, float hi) {
    __nv_bfloat162 t = __floats2bfloat162_rn(lo, hi);
    return *reinterpret_cast<uint32_t*>(&t);
}
__device__ __forceinline__ float2 unpackbf(uint32_t u) {
    __nv_bfloat162 t = *reinterpret_cast<__nv_bfloat162*>(&u);
    return make_float2(__bfloat162float(t.x), __bfloat162float(t.y));
}
__device__ __forceinline__ void mma_bf16(float c[4], const uint32_t a[4], const uint32_t b[2]) {
    asm volatile(
        "mma.sync.aligned.m16n8k16.row.col.f32.bf16.bf16.f32 "
        "{%0,%1,%2,%3}, {%4,%5,%6,%7}, {%8,%9}, {%0,%1,%2,%3};\n"
        : "+f"(c[0]), "+f"(c[1]), "+f"(c[2]), "+f"(c[3])
        : "r"(a[0]), "r"(a[1]), "r"(a[2]), "r"(a[3]), "r"(b[0]), "r"(b[1]));
}
__device__ __forceinline__ void atomicMinFloat(float* addr, float value) {
    if (value >= 0.f) atomicMin((int*)addr, __float_as_int(value));
    else              atomicMax((unsigned int*)addr, __float_as_uint(value));
}
__device__ __forceinline__ void cpa16(void* s, const uint32_t* g) {
    uint32_t sa = (uint32_t)__cvta_generic_to_shared(s);
    asm volatile("cp.async.cg.shared.global [%0], [%1], 16;" :: "r"(sa), "l"(g));
}
#define CP_COMMIT() asm volatile("cp.async.commit_group;")
#define CP_WAIT1()  asm volatile("cp.async.wait_group 1;")
#define CP_WAIT0()  asm volatile("cp.async.wait_group 0;")

typedef uint32_t Tile16[16][136];
#define TILE_WORDS (16 * 136)
#define SMEM_GEMM  (6 * TILE_WORDS * 4)   /* 52224 bytes: 3 stages x (A,B) */

// issue one 16-row x 128-col uint32 tile per operand (2x cp.async 16B per thread each)
#define ISSUE_TILE(DA, DB, SA, STA, SB, STB)                                   \
    _Pragma("unroll")                                                          \
    for (int it = 0; it < 2; it++) {                                           \
        int li = threadIdx.x + it * 256;                                       \
        int row = li >> 5, c4 = (li & 31) * 4;                                 \
        cpa16(&DA[row][c4], (SA) + (size_t)row * (STA) + c4);                  \
        cpa16(&DB[row][c4], (SB) + (size_t)row * (STB) + c4);                  \
    }

// 3-stage pipeline over NSTEP 32-k chunks (16 pair rows each)
#define PIPE_LOOP(NSTEP, STA, STB)                                             \
    ISSUE_TILE(As[0], Bs[0], srcA0, (STA), srcB0, (STB));                      \
    CP_COMMIT();                                                               \
    if (1 < (NSTEP)) {                                                         \
        const uint32_t* sa_ = srcA0 + (size_t)16 * (STA);                      \
        const uint32_t* sb_ = srcB0 + (size_t)16 * (STB);                      \
        ISSUE_TILE(As[1], Bs[1], sa_, (STA), sb_, (STB));                      \
        CP_COMMIT();                                                           \
    }                                                                          \
    {                                                                          \
        int buf = 0, nbuf = 2;                                                 \
        for (int s = 0; s < (NSTEP); s++) {                                    \
            if (s + 1 < (NSTEP)) { CP_WAIT1(); } else { CP_WAIT0(); }          \
            __syncthreads();                                                   \
            if (s + 2 < (NSTEP)) {                                             \
                const uint32_t* sa_ = srcA0 + (size_t)(s + 2) * 16 * (STA);    \
                const uint32_t* sb_ = srcB0 + (size_t)(s + 2) * 16 * (STB);    \
                ISSUE_TILE(As[nbuf], Bs[nbuf], sa_, (STA), sb_, (STB));        \
                CP_COMMIT();                                                   \
            }                                                                  \
            FRAG_MMA_LOOP(As[buf], Bs[buf])                                    \
            buf = (buf == 2) ? 0 : buf + 1;                                    \
            nbuf = (nbuf == 2) ? 0 : nbuf + 1;                                 \
        }                                                                      \
    }

// fragment compute: tile 128x128, k=32 (16 pair rows), 8 warps (4x2), 2x8 m16n8k16
#define FRAG_MMA_LOOP(AS, BS)                                                  \
    _Pragma("unroll")                                                          \
    for (int kk = 0; kk < 2; kk++) {                                           \
        const int kpb = kk * 8;                                                \
        uint32_t af[2][4], bfr[8][2];                                          \
        _Pragma("unroll")                                                      \
        for (int i = 0; i < 2; i++) {                                          \
            int mm = warp_m * 32 + i * 16 + r;                                 \
            af[i][0] = AS[kpb + cc][mm];                                       \
            af[i][1] = AS[kpb + cc][mm + 8];                                   \
            af[i][2] = AS[kpb + cc + 4][mm];                                   \
            af[i][3] = AS[kpb + cc + 4][mm + 8];                               \
        }                                                                      \
        _Pragma("unroll")                                                      \
        for (int j = 0; j < 8; j++) {                                          \
            int nn2 = warp_n * 64 + j * 8 + r;                                 \
            bfr[j][0] = BS[kpb + cc][nn2];                                     \
            bfr[j][1] = BS[kpb + cc + 4][nn2];                                 \
        }                                                                      \
        _Pragma("unroll")                                                      \
        for (int i = 0; i < 2; i++)                                            \
            _Pragma("unroll")                                                  \
            for (int j = 0; j < 8; j++) mma_bf16(acc[i][j], af[i], bfr[j]);    \
    }

#define ACC_INIT()                                                             \
    float acc[2][8][4];                                                        \
    _Pragma("unroll")                                                          \
    for (int i = 0; i < 2; i++)                                                \
        _Pragma("unroll")                                                      \
        for (int j = 0; j < 8; j++)                                            \
            _Pragma("unroll")                                                  \
            for (int q = 0; q < 4; q++) acc[i][j][q] = 0.f;

#define WARP_VARS()                                                            \
    const int tid = threadIdx.x;                                               \
    const int lane = tid & 31, wid = tid >> 5;                                 \
    const int warp_m = wid >> 1, warp_n = wid & 1;                             \
    const int r = lane >> 2, cc = lane & 3;

#define SMEM_TILES()                                                           \
    extern __shared__ uint32_t dyn_smem[];                                     \
    Tile16* As = reinterpret_cast<Tile16*>(dyn_smem);                          \
    Tile16* Bs = reinterpret_cast<Tile16*>(dyn_smem + 3 * TILE_WORDS);

// ---------------- pack: weights + bias + stats reset ----------------
__global__ void pack_misc_kernel(const float* __restrict__ Wq, const float* __restrict__ bq,
                                 const float* __restrict__ Wk, const float* __restrict__ bk) {
    int idx = blockIdx.x * blockDim.x + threadIdx.x;
    if (idx < (CH / 2) * MQK) {
        int m = idx & (MQK - 1), kp = idx >> 9;
        float a = (m < CK) ? Wq[m * CH + 2 * kp]     : Wk[(m - CK) * CH + 2 * kp];
        float b = (m < CK) ? Wq[m * CH + 2 * kp + 1] : Wk[(m - CK) * CH + 2 * kp + 1];
        g_Wp[kp * MQK + m] = packbf(a, b);
    }
    if (idx < MQK) g_bias[idx] = (idx < CK) ? bq[idx] : bk[idx - CK];
    if (idx < BATCH * NN) {
        g_minv[idx] = FLT_MAX;
        g_s1[idx] = 0.f;
        g_s2[idx] = 0.f;
    }
}

// ---------------- pack: x -> pairs along C, [b][kp][n] ----------------
__global__ void pack_xk_kernel(const float* __restrict__ x) {
    int n = blockIdx.x * 256 + threadIdx.x;
    int kp = blockIdx.y, b = blockIdx.z;
    uint32_t v = 0;
    if (n < NN) {
        const float* xb = x + (size_t)b * CH * NN;
        v = packbf(xb[(size_t)(2 * kp) * NN + n], xb[(size_t)(2 * kp + 1) * NN + n]);
    }
    g_xk[((size_t)b * (CH / 2) + kp) * NPADC + n] = v;
}

// ---------------- pack: x -> transposed pairs along N, [b][mp][c] ----------------
__global__ void pack_xvT_kernel(const float* __restrict__ x) {
    __shared__ uint32_t T[32][33];
    int mp0 = blockIdx.x * 32;                // 27 tiles -> 864 rows
    int c0  = blockIdx.y * 32;
    int b   = blockIdx.z;
    int tx = threadIdx.x, ty = threadIdx.y;   // (32, 8)
    const float* xb = x + (size_t)b * CH * NN;
#pragma unroll
    for (int p = 0; p < 4; p++) {
        int c = c0 + p * 8 + ty;
        int m = 2 * (mp0 + tx);
        float f0 = 0.f, f1 = 0.f;
        if (m < NN)     f0 = xb[(size_t)c * NN + m];
        if (m + 1 < NN) f1 = xb[(size_t)c * NN + m + 1];
        T[tx][p * 8 + ty] = packbf(f0, f1);
    }
    __syncthreads();
#pragma unroll
    for (int p = 0; p < 4; p++) {
        int row = p * 8 + ty;
        g_xvT[((size_t)b * NPP + mp0 + row) * CH + c0 + tx] = T[row][tx];
    }
}

// =====================================================================
// GEMM1: QK = Wqk @ xf + bias -> bf16 (m, m+8)-pairs  [b][pg][n]
// =====================================================================
__global__ __launch_bounds__(256, 2) void gemm1_kernel() {
    SMEM_TILES();
    const int b  = blockIdx.z;
    const int m0 = blockIdx.y * 128;
    const int n0 = blockIdx.x * 128;
    WARP_VARS();
    ACC_INIT();

    const uint32_t* srcA0 = g_Wp + (size_t)0 * MQK + m0;
    const uint32_t* srcB0 = g_xk + (size_t)b * (CH / 2) * NPADC + n0;

    PIPE_LOOP(CH / 32, MQK, NPADC)

    uint32_t* outp = g_QKp + (size_t)b * 256 * NPADC;
#pragma unroll
    for (int i = 0; i < 2; i++) {
        int m_lo = m0 + warp_m * 32 + i * 16 + r;
        int pg = (m_lo >> 4) * 8 + r;
        float b_lo = g_bias[m_lo], b_hi = g_bias[m_lo + 8];
#pragma unroll
        for (int j = 0; j < 8; j++) {
            int n = n0 + warp_n * 64 + j * 8 + 2 * cc;
            uint2 u;
            u.x = packbf(acc[i][j][0] + b_lo, acc[i][j][2] + b_hi);
            u.y = packbf(acc[i][j][1] + b_lo, acc[i][j][3] + b_hi);
            *reinterpret_cast<uint2*>(&outp[(size_t)pg * NPADC + n]) = u;
        }
    }
}

// =====================================================================
// GEMM2: P = (Q^T K)*scale*fg -> bf16 pairs [b][n][mp] + fused row stats
// =====================================================================
__global__ __launch_bounds__(256, 2) void gemm2_kernel(const float* __restrict__ fg) {
    SMEM_TILES();
    const int b  = blockIdx.z;
    const int n0 = blockIdx.y * 128;
    const int m0 = blockIdx.x * 128;
    WARP_VARS();
    ACC_INIT();

    const uint32_t* srcA0 = g_QKp + (size_t)b * 256 * NPADC + n0;
    const uint32_t* srcB0 = g_QKp + ((size_t)b * 256 + 128) * NPADC + m0;

    PIPE_LOOP(CK / 32, NPADC, NPADC)

    const float* FG = fg + (size_t)b * NN * NN;
    uint32_t* Pp = g_P + (size_t)b * NN * NPP;
#pragma unroll
    for (int i = 0; i < 2; i++)
#pragma unroll
        for (int h = 0; h < 2; h++) {
            int gn = n0 + warp_m * 32 + i * 16 + r + h * 8;
            bool rowvalid = gn < NN;
            size_t rowoff = (size_t)gn * NN;
            float mn = FLT_MAX, s1 = 0.f, s2 = 0.f;
#pragma unroll
            for (int j = 0; j < 8; j++) {
                int gm = m0 + warp_n * 64 + j * 8 + 2 * cc;
                if (rowvalid && gm < NN) {
                    float f0 = FG[rowoff + gm];
                    float p0 = acc[i][j][2 * h] * SCALE * f0;
                    mn = fminf(mn, p0); s1 += p0 * f0; s2 += f0;
                    float p1 = 0.f;
                    if (gm + 1 < NN) {
                        float f1 = FG[rowoff + gm + 1];
                        p1 = acc[i][j][2 * h + 1] * SCALE * f1;
                        mn = fminf(mn, p1); s1 += p1 * f1; s2 += f1;
                    }
                    Pp[(size_t)gn * NPP + (gm >> 1)] = packbf(p0, p1);
                }
            }
            mn = fminf(mn, __shfl_xor_sync(0xffffffffu, mn, 1));
            mn = fminf(mn, __shfl_xor_sync(0xffffffffu, mn, 2));
            s1 += __shfl_xor_sync(0xffffffffu, s1, 1);
            s1 += __shfl_xor_sync(0xffffffffu, s1, 2);
            s2 += __shfl_xor_sync(0xffffffffu, s2, 1);
            s2 += __shfl_xor_sync(0xffffffffu, s2, 2);
            if (cc == 0 && rowvalid) {
                atomicMinFloat(&g_minv[b * NN + gn], mn);
                atomicAdd(&g_s1[b * NN + gn], s1);
                atomicAdd(&g_s2[b * NN + gn], s2);
            }
        }
}

// =====================================================================
// simf: sim_final = (P - min)*fg*inv + bg -> bf16 pairs TRANSPOSED [b][mp][n]
// =====================================================================
__global__ void simf_kernel(const float* __restrict__ fg, const float* __restrict__ bg) {
    __shared__ uint32_t T[32][33];
    __shared__ float sMin[32], sInv[32];
    const int mp0 = blockIdx.x * 32;          // 27 tiles -> 864 rows
    const int n0  = blockIdx.y * 32;          // 53 tiles -> 1696
    const int b   = blockIdx.z;
    const int tx = threadIdx.x, ty = threadIdx.y;
    const int tid = ty * 32 + tx;

    if (tid < 32) {
        int n = n0 + tid;
        if (n < NN) {
            float mn = g_minv[b * NN + n];
            sMin[tid] = mn;
            sInv[tid] = 1.f / (g_s1[b * NN + n] - mn * g_s2[b * NN + n] + EPSV);
        } else {
            sMin[tid] = 0.f; sInv[tid] = 0.f;
        }
    }
    __syncthreads();

    const float* FG = fg + (size_t)b * NN * NN;
    const float* BG = bg + (size_t)b * NN * NN;
    const uint32_t* Pp = g_P + (size_t)b * NN * NPP;
#pragma unroll
    for (int p = 0; p < 4; p++) {
        int ny = p * 8 + ty;
        int n = n0 + ny;
        int mp = mp0 + tx, m = 2 * mp;
        float v0 = 0.f, v1 = 0.f;
        if (n < NN && m < NN) {
            float2 pv = unpackbf(Pp[(size_t)n * NPP + mp]);
            size_t a = (size_t)n * NN + m;
            float mn = sMin[ny], inv = sInv[ny];
            v0 = (pv.x - mn) * FG[a] * inv + BG[a];
            if (m + 1 < NN)
                v1 = (pv.y - mn) * FG[a + 1] * inv + BG[a + 1];
        }
        T[tx][ny] = packbf(v0, v1);
    }
    __syncthreads();
#pragma unroll
    for (int p = 0; p < 4; p++) {
        int row = p * 8 + ty;
        g_simfT[((size_t)b * NPP + mp0 + row) * NPADC + n0 + tx] = T[row][tx];
    }
}

// =====================================================================
// GEMM3 (transposed): out[c][n] = gamma * sum_m V_pair @ simf_T + x[c][n]
// =====================================================================
__global__ __launch_bounds__(256, 2) void gemm3_kernel(const float* __restrict__ x,
                                                       const float* __restrict__ gamma,
                                                       float* __restrict__ out) {
    SMEM_TILES();
    const int b  = blockIdx.z;
    const int c0 = blockIdx.x * 128;
    const int n0 = blockIdx.y * 128;
    WARP_VARS();
    ACC_INIT();

    const uint32_t* srcA0 = g_xvT   + (size_t)b * NPP * CH + c0;
    const uint32_t* srcB0 = g_simfT + (size_t)b * NPP * NPADC + n0;

    PIPE_LOOP(53, CH, NPADC)   // 53*16 = 848 pair rows >= ceil(1681/2)

    const float g = gamma[0];
    const float* xf = x + (size_t)b * CH * NN;
    float* outb = out + (size_t)b * CH * NN;
#pragma unroll
    for (int i = 0; i < 2; i++)
#pragma unroll
        for (int h = 0; h < 2; h++) {
            int gc = c0 + warp_m * 32 + i * 16 + r + h * 8;
            size_t rowoff = (size_t)gc * NN;
#pragma unroll
            for (int j = 0; j < 8; j++) {
                int gn = n0 + warp_n * 64 + j * 8 + 2 * cc;
                if (gn < NN)
                    outb[rowoff + gn]     = g * acc[i][j][2 * h]     + xf[rowoff + gn];
                if (gn + 1 < NN)
                    outb[rowoff + gn + 1] = g * acc[i][j][2 * h + 1] + xf[rowoff + gn + 1];
            }
        }
}

// ---------------- launch ----------------
extern "C" void kernel_launch(void* const* d_in, const int* in_sizes, int n_in,
                              void* d_out, int out_size) {
    const float* x     = (const float*)d_in[0];
    const float* fg    = (const float*)d_in[1];
    const float* bg    = (const float*)d_in[2];
    const float* Wq    = (const float*)d_in[3];
    const float* bq    = (const float*)d_in[4];
    const float* Wk    = (const float*)d_in[5];
    const float* bk    = (const float*)d_in[6];
    const float* gamma = (const float*)d_in[7];
    float* out = (float*)d_out;

    static bool attr_done = false;
    if (!attr_done) {
        cudaFuncSetAttribute(gemm1_kernel, cudaFuncAttributeMaxDynamicSharedMemorySize, SMEM_GEMM);
        cudaFuncSetAttribute(gemm2_kernel, cudaFuncAttributeMaxDynamicSharedMemorySize, SMEM_GEMM);
        cudaFuncSetAttribute(gemm3_kernel, cudaFuncAttributeMaxDynamicSharedMemorySize, SMEM_GEMM);
        attr_done = true;
    }

    pack_misc_kernel<<<((CH / 2) * MQK + 255) / 256, 256>>>(Wq, bq, Wk, bk);
    pack_xk_kernel<<<dim3(7, CH / 2, BATCH), 256>>>(x);
    pack_xvT_kernel<<<dim3(27, 16, BATCH), dim3(32, 8)>>>(x);

    gemm1_kernel<<<dim3(14, 4, BATCH), 256, SMEM_GEMM>>>();
    gemm2_kernel<<<dim3(14, 14, BATCH), 256, SMEM_GEMM>>>(fg);
    simf_kernel<<<dim3(27, 53, BATCH), dim3(32, 8)>>>(fg, bg);
    gemm3_kernel<<<dim3(4, 14, BATCH), 256, SMEM_GEMM>>>(x, gamma, out);
}